// round 15
// baseline (speedup 1.0000x reference)
#include <cuda_runtime.h>
#include <cuda_bf16.h>
#include <cstdint>

#define Bsz 4
#define Ssz 128
#define Esz 512
#define Hn 8
#define HDsz 64
#define FFsz 2048
#define Lnum 4
#define Msz (Bsz*Ssz)   /* 512 rows */
#define KEXT 288        /* packed attn K: 128 + 128 + 11 -> pad 288 */
#define QKVN (4*Msz*Esz)    /* 1048576 */
#define KPN  (1000*Esz)     /* 512000 */

// ===================== scratch (static device memory) ======================
__device__ float g_h[Msz*Esz];
__device__ float g_qkv[4*Msz*Esz];
__device__ float g_kproj[1024*Esz];
__device__ float g_ff[Msz*FFsz];
__device__ float g_part[4*512*512];
__device__ float g_qk[Bsz*Hn*Ssz*Ssz];
__device__ float g_asump[2*Msz*Esz];         // gemm_attn K-split partials
__device__ float g_qkp[512*8000];
__device__ float g_Aext[Bsz*Hn*Ssz*KEXT];
__device__ float g_Wext[Bsz*Hn*HDsz*KEXT];
__device__ float g_partA[2*(QKVN+KPN)];      // layer_a / ffn1 split-K partials

// ===================== helpers ==============================================
__device__ __forceinline__ void split1(float x, unsigned short& h, unsigned short& l)
{
    __nv_bfloat16 hb = __float2bfloat16(x);
    h = __bfloat16_as_ushort(hb);
    l = __bfloat16_as_ushort(__float2bfloat16(x - __bfloat162float(hb)));
}
__device__ __forceinline__ void ldsm_x4(uint32_t& r0, uint32_t& r1,
                                        uint32_t& r2, uint32_t& r3, uint32_t addr)
{
    asm volatile("ldmatrix.sync.aligned.m8n8.x4.shared.b16 {%0,%1,%2,%3}, [%4];"
                 : "=r"(r0), "=r"(r1), "=r"(r2), "=r"(r3) : "r"(addr));
}
__device__ __forceinline__ void mma_bf16(float* c, const uint32_t* a, const uint32_t* b)
{
    asm volatile("mma.sync.aligned.m16n8k16.row.col.f32.bf16.bf16.f32 "
                 "{%0,%1,%2,%3},{%4,%5,%6,%7},{%8,%9},{%0,%1,%2,%3};"
                 : "+f"(c[0]), "+f"(c[1]), "+f"(c[2]), "+f"(c[3])
                 : "r"(a[0]), "r"(a[1]), "r"(a[2]), "r"(a[3]), "r"(b[0]), "r"(b[1]));
}
__device__ __forceinline__ uint32_t smem_u32(const void* p) {
    uint32_t a;
    asm("{ .reg .u64 t; cvta.to.shared.u64 t, %1; cvt.u32.u64 %0, t; }" : "=r"(a) : "l"(p));
    return a;
}

// ===================== tensor-core bf16x3 GEMM (BK=32) ======================
#define BK 32
#define LDSE 40
#define PARTB (64*LDSE*2)
#define STAGEB (4*PARTB)

__device__ __forceinline__ void load_chunk(
    const float* __restrict__ A, const float* __restrict__ A2, int lda,
    int row0a, int Ma,
    const float* __restrict__ W, int ldw, int row0w, int Nw,
    int k0, int tid, float4* ra, float4* rw)
{
    int r = tid >> 1, half = tid & 1;
    int ga = min(row0a + r, Ma - 1);
    int gw = min(row0w + r, Nw - 1);
    const float4* pa = (const float4*)(A + (size_t)ga * lda + k0 + half * 16);
    const float4* pw = (const float4*)(W + (size_t)gw * ldw + k0 + half * 16);
    #pragma unroll
    for (int u = 0; u < 4; u++) { ra[u] = pa[u]; rw[u] = pw[u]; }
    if (A2) {
        const float4* p2 = (const float4*)(A2 + (size_t)ga * lda + k0 + half * 16);
        #pragma unroll
        for (int u = 0; u < 4; u++) {
            float4 t = p2[u];
            ra[u].x += t.x; ra[u].y += t.y; ra[u].z += t.z; ra[u].w += t.w;
        }
    }
}

__device__ __forceinline__ void store_chunk(uint32_t s_hi, uint32_t s_lo,
                                            const float4* rv, int tid)
{
    int r = tid >> 1, half = tid & 1;
    uint32_t off = (uint32_t)r * (LDSE * 2) + half * 32;
    #pragma unroll
    for (int u = 0; u < 4; u++) {
        float4 v = rv[u];
        ushort4 hh, ll;
        split1(v.x, hh.x, ll.x); split1(v.y, hh.y, ll.y);
        split1(v.z, hh.z, ll.z); split1(v.w, hh.w, ll.w);
        asm volatile("st.shared.v4.u16 [%0], {%1,%2,%3,%4};"
                     :: "r"(s_hi + off + u * 8), "h"(hh.x), "h"(hh.y), "h"(hh.z), "h"(hh.w));
        asm volatile("st.shared.v4.u16 [%0], {%1,%2,%3,%4};"
                     :: "r"(s_lo + off + u * 8), "h"(ll.x), "h"(ll.y), "h"(ll.z), "h"(ll.w));
    }
}

__device__ __forceinline__ void gemm_mma_body(
    const float* __restrict__ A, const float* __restrict__ A2, int lda,
    const float* __restrict__ W, int ldw,
    const float* __restrict__ bias, float* __restrict__ C, size_t ldcr, int ldcc,
    int bm, int bn, int M, int N, int kbeg, int kend, int act)
{
    __shared__ __align__(16) char smem[2 * STAGEB];
    uint32_t sb = smem_u32(smem);
    int tid = threadIdx.x;                  // 128
    int lane = tid & 31, wid = tid >> 5;
    int wm = wid >> 1, wn = wid & 1;

    float acc[2][4][4] = {};

    uint32_t a_off = ((uint32_t)(wm * 32 + (lane & 15)) * LDSE + ((lane & 16) >> 1)) * 2;
    uint32_t b_off = ((uint32_t)(wn * 32 + (lane & 7) + ((lane & 16) >> 1)) * LDSE) * 2
                     + (lane & 8) * 2;

    int nch = (kend - kbeg) / BK;
    float4 ra[4], rw[4];
    load_chunk(A, A2, lda, bm, M, W, ldw, bn, N, kbeg, tid, ra, rw);
    store_chunk(sb, sb + PARTB, ra, tid);
    store_chunk(sb + 2 * PARTB, sb + 3 * PARTB, rw, tid);

    for (int c = 0; c < nch; c++) {
        uint32_t cb = sb + (uint32_t)(c & 1) * STAGEB;
        __syncthreads();
        bool more = (c + 1 < nch);
        if (more)
            load_chunk(A, A2, lda, bm, M, W, ldw, bn, N, kbeg + (c + 1) * BK, tid, ra, rw);
        #pragma unroll
        for (int ks = 0; ks < 2; ks++) {
            uint32_t a_hi[2][4], a_lo[2][4], b_hi[4][2], b_lo[4][2];
            #pragma unroll
            for (int tm = 0; tm < 2; tm++) {
                uint32_t ad = cb + a_off + (uint32_t)tm * 16 * LDSE * 2 + ks * 32;
                ldsm_x4(a_hi[tm][0], a_hi[tm][1], a_hi[tm][2], a_hi[tm][3], ad);
                ldsm_x4(a_lo[tm][0], a_lo[tm][1], a_lo[tm][2], a_lo[tm][3], ad + PARTB);
            }
            #pragma unroll
            for (int tp = 0; tp < 2; tp++) {
                uint32_t bd = cb + 2 * PARTB + b_off
                            + (uint32_t)tp * 16 * LDSE * 2 + ks * 32;
                ldsm_x4(b_hi[2*tp][0], b_hi[2*tp][1], b_hi[2*tp+1][0], b_hi[2*tp+1][1], bd);
                ldsm_x4(b_lo[2*tp][0], b_lo[2*tp][1], b_lo[2*tp+1][0], b_lo[2*tp+1][1],
                        bd + PARTB);
            }
            #pragma unroll
            for (int tm = 0; tm < 2; tm++)
                #pragma unroll
                for (int tn = 0; tn < 4; tn++) {
                    mma_bf16(acc[tm][tn], a_hi[tm], b_hi[tn]);
                    mma_bf16(acc[tm][tn], a_hi[tm], b_lo[tn]);
                    mma_bf16(acc[tm][tn], a_lo[tm], b_hi[tn]);
                }
        }
        if (more) {
            uint32_t nb = sb + (uint32_t)((c + 1) & 1) * STAGEB;
            store_chunk(nb, nb + PARTB, ra, tid);
            store_chunk(nb + 2 * PARTB, nb + 3 * PARTB, rw, tid);
        }
    }

    int mrow = bm + wm * 32 + (lane >> 2);
    int ncol = bn + wn * 32 + (lane & 3) * 2;
    #pragma unroll
    for (int tm = 0; tm < 2; tm++) {
        #pragma unroll
        for (int half = 0; half < 2; half++) {
            int m = mrow + tm * 16 + half * 8;
            if (m >= M) continue;
            size_t rb = (size_t)m * ldcr;
            #pragma unroll
            for (int tn = 0; tn < 4; tn++) {
                int n = ncol + tn * 8;
                float v0 = acc[tm][tn][half * 2 + 0];
                float v1 = acc[tm][tn][half * 2 + 1];
                if (bias) { v0 += bias[n]; v1 += bias[n + 1]; }
                if (act) { v0 = fmaxf(v0, 0.f); v1 = fmaxf(v1, 0.f); }
                if (ldcc == 1 && n + 1 < N) {
                    *(float2*)(C + rb + n) = make_float2(v0, v1);
                } else {
                    if (n < N)     C[rb + (size_t)n * ldcc]       = v0;
                    if (n + 1 < N) C[rb + (size_t)(n + 1) * ldcc] = v1;
                }
            }
        }
    }
}

// ===================== global kernels ========================================
__global__ void __launch_bounds__(128) gemm_tc_splitk(
    const float* A, const float* W, float* part, int M, int N, int K, int KS)
{
    int chunk = K / KS;
    int z = blockIdx.z;
    gemm_mma_body(A, nullptr, K, W, K, nullptr, part + (size_t)z * M * N, N, 1,
                  blockIdx.y * 64, blockIdx.x * 64, M, N, z * chunk, (z + 1) * chunk, 0);
}

// Wo projection with A = slab0 + slab1, split-K
__global__ void __launch_bounds__(128) gemm_wo2(
    const float* A0, const float* A1s, const float* W, float* part,
    int M, int N, int K, int KS)
{
    int chunk = K / KS;
    int z = blockIdx.z;
    gemm_mma_body(A0, A1s, K, W, K, nullptr, part + (size_t)z * M * N, N, 1,
                  blockIdx.y * 64, blockIdx.x * 64, M, N, z * chunk, (z + 1) * chunk, 0);
}

// fused q/k/vs/vo + knowledge projections, split-K=2: grid (384,1,2)
__global__ void __launch_bounds__(128) gemm_layer_a(
    const float* __restrict__ h, const float* __restrict__ knowledge,
    const float* __restrict__ W0, const float* __restrict__ W1,
    const float* __restrict__ W2, const float* __restrict__ W3,
    const float* __restrict__ Wkn,
    float* __restrict__ partA)
{
    int idx = blockIdx.x;
    int kh = blockIdx.z;
    int kbeg = kh * 256, kend = kbeg + 256;
    float* base = partA + (size_t)kh * (QKVN + KPN);
    if (idx < 256) {
        int z = idx >> 6, t = idx & 63;
        const float* W = (z == 0) ? W0 : (z == 1) ? W1 : (z == 2) ? W2 : W3;
        gemm_mma_body(h, nullptr, Esz, W, Esz, nullptr,
                      base + (size_t)z * Msz * Esz, Esz, 1,
                      (t >> 3) * 64, (t & 7) * 64, Msz, Esz, kbeg, kend, 0);
    } else {
        int t = idx - 256;
        gemm_mma_body(knowledge, nullptr, Esz, Wkn, Esz, nullptr,
                      base + QKVN, Esz, 1,
                      (t >> 3) * 64, (t & 7) * 64, 1000, Esz, kbeg, kend, 0);
    }
}

// reduce layer_a partials -> qkv + kproj
__global__ void reduce_qkv(const float* __restrict__ pa,
                           float* __restrict__ qkv, float* __restrict__ kproj)
{
    const int TOT = QKVN + KPN;
    int i = (blockIdx.x * 256 + threadIdx.x) * 4;
    if (i >= TOT) return;
    float4 a = *(const float4*)(pa + i);
    float4 b = *(const float4*)(pa + (size_t)TOT + i);
    a.x += b.x; a.y += b.y; a.z += b.z; a.w += b.w;
    if (i < QKVN) *(float4*)(qkv + i) = a;
    else          *(float4*)(kproj + (i - QKVN)) = a;
}

// reduce ffn1 partials (+bias+relu) -> ff
__global__ void reduce_ff(const float* __restrict__ part,
                          const float* __restrict__ bias, float* __restrict__ out)
{
    const int MN = Msz * FFsz;
    int i = (blockIdx.x * 256 + threadIdx.x) * 4;
    if (i >= MN) return;
    float4 a = *(const float4*)(part + i);
    float4 b = *(const float4*)(part + (size_t)MN + i);
    int n = i % FFsz;
    a.x = fmaxf(a.x + b.x + bias[n], 0.f);
    a.y = fmaxf(a.y + b.y + bias[n + 1], 0.f);
    a.z = fmaxf(a.z + b.z + bias[n + 2], 0.f);
    a.w = fmaxf(a.w + b.w + bias[n + 3], 0.f);
    *(float4*)(out + i) = a;
}

// combined qk + qkp (double-buffered BK=32 body): grid (18, 2, 32)
__global__ void __launch_bounds__(128) gemm_qkqkp(
    const float* __restrict__ q, const float* __restrict__ k,
    const float* __restrict__ kproj,
    float* __restrict__ qk, float* __restrict__ qkp)
{
    int z = blockIdx.z, b = z >> 3, h = z & 7;
    const float* qa = q + (size_t)b * Ssz * Esz + h * HDsz;
    int bm = blockIdx.y * 64;
    if (blockIdx.x < 16) {
        gemm_mma_body(qa, nullptr, Esz, kproj + h * HDsz, Esz, nullptr,
                      qkp + (size_t)b * Ssz * 8000 + h, 8000, 8,
                      bm, blockIdx.x * 64, Ssz, 1000, 0, HDsz, 0);
    } else {
        gemm_mma_body(qa, nullptr, Esz, k + (size_t)b * Ssz * Esz + h * HDsz, Esz,
                      nullptr, qk + (size_t)z * Ssz * Ssz, Ssz, 1,
                      bm, (blockIdx.x - 16) * 64, Ssz, Ssz, 0, HDsz, 0);
    }
}

// attention value GEMM, K-split over KEXT: grid (2, 2, 32) = 128 CTAs
__global__ void __launch_bounds__(128) gemm_attn(
    const float* __restrict__ Aext, const float* __restrict__ Wext,
    float* __restrict__ partout)
{
    int z2 = blockIdx.x;
    int z = blockIdx.z, b = z >> 3, h = z & 7;
    int kbeg = z2 ? 160 : 0;
    int kend = z2 ? 288 : 160;
    gemm_mma_body(Aext + (size_t)z * Ssz * KEXT, nullptr, KEXT,
                  Wext + (size_t)z * HDsz * KEXT, KEXT,
                  nullptr,
                  partout + (size_t)z2 * Msz * Esz + (size_t)b * Ssz * Esz + h * HDsz,
                  Esz, 1, blockIdx.y * 64, 0, Ssz, HDsz, kbeg, kend, 0);
}

// ======== combined scores (blocks 0..511) + W_ext pack (blocks 512..543) ====
__global__ void __launch_bounds__(256) scores_pack(
    const float* __restrict__ qk, const float* __restrict__ qkp,
    const float* __restrict__ q,
    const int* __restrict__ know_adj, const int* __restrict__ pos_mask,
    const int* __restrict__ adj,
    const int* __restrict__ smk, const int* __restrict__ omk,
    const float* __restrict__ pe_k,
    const float* __restrict__ vs, const float* __restrict__ vo,
    const float* __restrict__ pe_v,
    float* __restrict__ Aext, float* __restrict__ Wext)
{
    __shared__ float sh[128 * 65];
    int blk = blockIdx.x;
    int tid = threadIdx.x;

    if (blk >= 512) {
        int z = blk - 512, b = z >> 3, h = z & 7;
        float* vsh = sh;
        float* wbase = Wext + (size_t)z * HDsz * KEXT;
        for (int idx = tid; idx < 128 * 64; idx += 256) {
            int j = idx >> 6, d = idx & 63;
            vsh[j * 65 + d] = vs[(size_t)(b * Ssz + j) * Esz + h * HDsz + d];
        }
        __syncthreads();
        {
            int w = tid >> 5, l = tid & 31;
            #pragma unroll
            for (int r = 0; r < 8; r++) {
                int d = w * 8 + r;
                float* dst = wbase + (size_t)d * KEXT;
                #pragma unroll
                for (int t = 0; t < 4; t++) {
                    int j = l + 32 * t;
                    dst[j] = vsh[j * 65 + d];
                }
            }
        }
        __syncthreads();
        for (int idx = tid; idx < 128 * 64; idx += 256) {
            int j = idx >> 6, d = idx & 63;
            vsh[j * 65 + d] = vo[(size_t)(b * Ssz + j) * Esz + h * HDsz + d];
        }
        __syncthreads();
        {
            int w = tid >> 5, l = tid & 31;
            #pragma unroll
            for (int r = 0; r < 8; r++) {
                int d = w * 8 + r;
                float* dst = wbase + (size_t)d * KEXT + 128;
                #pragma unroll
                for (int t = 0; t < 4; t++) {
                    int j = l + 32 * t;
                    dst[j] = vsh[j * 65 + d];
                }
            }
        }
        for (int idx = tid; idx < 64 * 32; idx += 256) {
            int d = idx >> 5, c = idx & 31;
            float v = (c < 11) ? pe_v[c * HDsz + d] : 0.f;
            wbase[(size_t)d * KEXT + 256 + c] = v;
        }
        return;
    }

    int i = blk & 127, b = blk >> 7;
    float* q_sh   = sh;
    float* qk_sh  = sh + 512;
    float* qkp_sh = sh + 1536;
    float* qr     = sh + 2688;
    int*   ka_sh  = (int*)(sh + 2776);
    int*   p_sh   = (int*)(sh + 2904);

    q_sh[tid]       = q[(size_t)(b * Ssz + i) * Esz + tid];
    q_sh[tid + 256] = q[(size_t)(b * Ssz + i) * Esz + tid + 256];
    if (tid < 128) {
        int ka = know_adj[(size_t)(b * Ssz + i) * Ssz + tid];
        ka_sh[tid] = min(max(ka, 0), 999);
        int p = pos_mask[i * Ssz + tid];
        p_sh[tid] = min(max(p, 0), 10);
    }
    {
        int h = tid >> 5, j4 = (tid & 31) * 4;
        float4 v = *(const float4*)(qk + ((size_t)(b * Hn + h) * Ssz + i) * Ssz + j4);
        *(float4*)(qk_sh + h * 128 + j4) = v;
    }
    if (tid < 168) {
        int h = tid / 21, c = tid % 21;
        Aext[((size_t)(b * Hn + h) * Ssz + i) * KEXT + 267 + c] = 0.f;
    }
    __syncthreads();

    {
        int j = tid >> 1, half = tid & 1;
        float4 g = *(const float4*)(qkp + (size_t)(b * Ssz + i) * 8000
                                    + ka_sh[j] * 8 + half * 4);
        float* dst = qkp_sh + j * 9 + half * 4;
        dst[0] = g.x; dst[1] = g.y; dst[2] = g.z; dst[3] = g.w;
    }
    if (tid < 88) {
        int h = tid / 11, p = tid % 11;
        float s = 0.f;
        const float4* pk = (const float4*)(pe_k + p * HDsz);
        const float4* qv = (const float4*)(q_sh + h * 64);
        #pragma unroll
        for (int v = 0; v < 16; v++) {
            float4 e = pk[v], qq = qv[v];
            s += qq.x * e.x + qq.y * e.y + qq.z * e.z + qq.w * e.w;
        }
        qr[h * 11 + p] = s;
    }
    __syncthreads();

    {
        int w = tid >> 5, l = tid & 31;
        float s[4];
        float m = -3.4e38f;
        #pragma unroll
        for (int t = 0; t < 4; t++) {
            int j = l + 32 * t;
            float ss = (qk_sh[w * 128 + j] + qkp_sh[j * 9 + w]
                        + qr[w * 11 + p_sh[j]]) * 0.125f;
            if (adj[(size_t)(b * Ssz + i) * Ssz + j] == 0) ss -= 1e30f;
            s[t] = ss;
            m = fmaxf(m, ss);
        }
        #pragma unroll
        for (int o = 16; o; o >>= 1) m = fmaxf(m, __shfl_xor_sync(0xffffffffu, m, o));
        float sum = 0.f;
        float e[4];
        #pragma unroll
        for (int t = 0; t < 4; t++) { e[t] = __expf(s[t] - m); sum += e[t]; }
        #pragma unroll
        for (int o = 16; o; o >>= 1) sum += __shfl_xor_sync(0xffffffffu, sum, o);
        float inv = 1.f / sum;
        size_t abase = ((size_t)(b * Hn + w) * Ssz + i) * KEXT;
        #pragma unroll
        for (int t = 0; t < 4; t++) {
            int j = l + 32 * t;
            float attn = e[t] * inv;
            Aext[abase + j]       = attn * (float)smk[(size_t)(b * Ssz + i) * Ssz + j];
            Aext[abase + 128 + j] = attn * (float)omk[(size_t)(b * Ssz + i) * Ssz + j];
            qk_sh[w * 128 + j] = attn;
        }
    }
    __syncthreads();

    if (tid < 88) {
        int h = tid / 11, p = tid % 11;
        float s = 0.f;
        for (int j = 0; j < 128; j++)
            if (p_sh[j] == p) s += qk_sh[h * 128 + j];
        Aext[((size_t)(b * Hn + h) * Ssz + i) * KEXT + 256 + p] = s;
    }
}

// ===== fused split-K reduce + bias + residual + layernorm ===================
__global__ void ln_red_kernel(const float* __restrict__ x, const float* __restrict__ part,
                              int KS, const float* __restrict__ bias,
                              const float* __restrict__ g, const float* __restrict__ bt,
                              float* __restrict__ dst)
{
    const int MN = Msz * Esz;
    int row = blockIdx.x;
    int tid = threadIdx.x;   // 256
    __shared__ float red[8];
    size_t i0 = (size_t)row * Esz + tid;
    size_t i1 = i0 + 256;
    float v0 = x[i0], v1 = x[i1];
    for (int z = 0; z < KS; z++) {
        v0 += part[(size_t)z * MN + i0];
        v1 += part[(size_t)z * MN + i1];
    }
    if (bias) { v0 += bias[tid]; v1 += bias[tid + 256]; }
    float s = v0 + v1;
    #pragma unroll
    for (int o = 16; o; o >>= 1) s += __shfl_xor_sync(0xffffffffu, s, o);
    if ((tid & 31) == 0) red[tid >> 5] = s;
    __syncthreads();
    float mean = 0.f;
    #pragma unroll
    for (int w = 0; w < 8; w++) mean += red[w];
    mean *= (1.f / 512.f);
    __syncthreads();
    float e0 = v0 - mean, e1 = v1 - mean;
    float s2 = e0 * e0 + e1 * e1;
    #pragma unroll
    for (int o = 16; o; o >>= 1) s2 += __shfl_xor_sync(0xffffffffu, s2, o);
    if ((tid & 31) == 0) red[tid >> 5] = s2;
    __syncthreads();
    float var = 0.f;
    #pragma unroll
    for (int w = 0; w < 8; w++) var += red[w];
    var *= (1.f / 512.f);
    float rstd = rsqrtf(var + 1e-5f);
    dst[i0] = e0 * rstd * g[tid] + bt[tid];
    dst[i1] = e1 * rstd * g[tid + 256] + bt[tid + 256];
}

// ===================== host orchestration ===================================
extern "C" void kernel_launch(void* const* d_in, const int* in_sizes, int n_in,
                              void* d_out, int out_size)
{
    const float* x        = (const float*)d_in[0];
    const int*   adj      = (const int*)d_in[1];
    const int*   smk      = (const int*)d_in[2];
    const int*   omk      = (const int*)d_in[3];
    const float* knowledge= (const float*)d_in[4];
    const int*   know_adj = (const int*)d_in[5];
    const int*   pos_mask = (const int*)d_in[6];
    const float* pe_k     = (const float*)d_in[7];
    const float* pe_v     = (const float*)d_in[8];
    const float* Wq       = (const float*)d_in[9];
    const float* Wk       = (const float*)d_in[10];
    const float* Wvs      = (const float*)d_in[11];
    const float* Wvo      = (const float*)d_in[12];
    const float* Wo       = (const float*)d_in[13];
    const float* Wkn      = (const float*)d_in[14];
    const float* ln1g     = (const float*)d_in[15];
    const float* ln1b     = (const float*)d_in[16];
    const float* w1       = (const float*)d_in[17];
    const float* b1       = (const float*)d_in[18];
    const float* w2       = (const float*)d_in[19];
    const float* b2       = (const float*)d_in[20];
    const float* ln2g     = (const float*)d_in[21];
    const float* ln2b     = (const float*)d_in[22];
    float* out = (float*)d_out;

    float *h, *qkv, *kproj, *ff, *part, *qkbuf, *asump, *qkp, *Aext, *Wext, *partA;
    cudaGetSymbolAddress((void**)&h, g_h);
    cudaGetSymbolAddress((void**)&qkv, g_qkv);
    cudaGetSymbolAddress((void**)&kproj, g_kproj);
    cudaGetSymbolAddress((void**)&ff, g_ff);
    cudaGetSymbolAddress((void**)&part, g_part);
    cudaGetSymbolAddress((void**)&qkbuf, g_qk);
    cudaGetSymbolAddress((void**)&asump, g_asump);
    cudaGetSymbolAddress((void**)&qkp, g_qkp);
    cudaGetSymbolAddress((void**)&Aext, g_Aext);
    cudaGetSymbolAddress((void**)&Wext, g_Wext);
    cudaGetSymbolAddress((void**)&partA, g_partA);

    const size_t EE = (size_t)Esz * Esz;
    const size_t FE = (size_t)FFsz * Esz;
    for (int l = 0; l < Lnum; l++) {
        const float* hin = (l == 0) ? x : h;
        const float* wq  = Wq  + (size_t)l * EE;
        const float* wk  = Wk  + (size_t)l * EE;
        const float* wvs = Wvs + (size_t)l * EE;
        const float* wvo = Wvo + (size_t)l * EE;
        const float* wo  = Wo  + (size_t)l * EE;
        const float* wkn = Wkn + (size_t)l * EE;

        // proj4 + kproj, split-K=2 (768 CTAs) + reduce
        gemm_layer_a<<<dim3(384, 1, 2), 128>>>(hin, knowledge, wq, wk, wvs, wvo, wkn,
                                               partA);
        reduce_qkv<<<(QKVN + KPN + 1023) / 1024, 256>>>(partA, qkv, kproj);
        // qk + qkp (1152 CTAs)
        gemm_qkqkp<<<dim3(18, 2, 32), 128>>>(qkv, qkv + (size_t)Msz * Esz, kproj,
                                             qkbuf, qkp);
        scores_pack<<<544, 256>>>(
            qkbuf, qkp, qkv, know_adj, pos_mask, adj, smk, omk, pe_k,
            qkv + 2 * (size_t)Msz * Esz, qkv + 3 * (size_t)Msz * Esz, pe_v,
            Aext, Wext);
        // attention value GEMM, K-split=2 -> partials (128 CTAs)
        gemm_attn<<<dim3(2, 2, 32), 128>>>(Aext, Wext, asump);
        // Wo projection summing attn partials on the fly, split-K=2
        gemm_wo2<<<dim3(8, 8, 2), 128>>>(asump, asump + (size_t)Msz * Esz, wo, part,
                                         Msz, Esz, Esz, 2);
        ln_red_kernel<<<Msz, 256>>>(hin, part, 2, nullptr,
                                    ln1g + l * Esz, ln1b + l * Esz, h);
        // FFN1 split-K=2 (512 CTAs) + reduce(bias+relu)
        gemm_tc_splitk<<<dim3(32, 8, 2), 128>>>(h, w1 + (size_t)l * FE, partA,
                                                Msz, FFsz, Esz, 2);
        reduce_ff<<<Msz * FFsz / 1024, 256>>>(partA, b1 + (size_t)l * FFsz, ff);
        // FFN2 split-K=4 + fused reduce+bias+LN2
        gemm_tc_splitk<<<dim3(8, 8, 4), 128>>>(ff, w2 + (size_t)l * FE, part,
                                               Msz, Esz, FFsz, 4);
        float* dst = (l == Lnum - 1) ? out : h;
        ln_red_kernel<<<Msz, 256>>>(h, part, 4, b2 + l * Esz,
                                    ln2g + l * Esz, ln2b + l * Esz, dst);
    }
}

// round 16
// speedup vs baseline: 1.0556x; 1.0556x over previous
#include <cuda_runtime.h>
#include <cuda_bf16.h>
#include <cstdint>

#define Bsz 4
#define Ssz 128
#define Esz 512
#define Hn 8
#define HDsz 64
#define FFsz 2048
#define Lnum 4
#define Msz (Bsz*Ssz)   /* 512 rows */
#define KEXT 288        /* packed attn K: 128 + 128 + 11 -> pad 288 */

// ===================== scratch (static device memory) ======================
__device__ float g_h[Msz*Esz];
__device__ float g_qkv[4*Msz*Esz];
__device__ float g_kproj[1024*Esz];
__device__ float g_ff[Msz*FFsz];
__device__ float g_part[4*512*512];
__device__ float g_qk[Bsz*Hn*Ssz*Ssz];
__device__ float g_asump[2*Msz*Esz];         // gemm_attn K-split partials
__device__ float g_qkp[512*8000];
__device__ float g_Aext[Bsz*Hn*Ssz*KEXT];
__device__ float g_Wext[Bsz*Hn*HDsz*KEXT];

// ===================== helpers ==============================================
__device__ __forceinline__ void split1(float x, unsigned short& h, unsigned short& l)
{
    __nv_bfloat16 hb = __float2bfloat16(x);
    h = __bfloat16_as_ushort(hb);
    l = __bfloat16_as_ushort(__float2bfloat16(x - __bfloat162float(hb)));
}
__device__ __forceinline__ void ldsm_x4(uint32_t& r0, uint32_t& r1,
                                        uint32_t& r2, uint32_t& r3, uint32_t addr)
{
    asm volatile("ldmatrix.sync.aligned.m8n8.x4.shared.b16 {%0,%1,%2,%3}, [%4];"
                 : "=r"(r0), "=r"(r1), "=r"(r2), "=r"(r3) : "r"(addr));
}
__device__ __forceinline__ void mma_bf16(float* c, const uint32_t* a, const uint32_t* b)
{
    asm volatile("mma.sync.aligned.m16n8k16.row.col.f32.bf16.bf16.f32 "
                 "{%0,%1,%2,%3},{%4,%5,%6,%7},{%8,%9},{%0,%1,%2,%3};"
                 : "+f"(c[0]), "+f"(c[1]), "+f"(c[2]), "+f"(c[3])
                 : "r"(a[0]), "r"(a[1]), "r"(a[2]), "r"(a[3]), "r"(b[0]), "r"(b[1]));
}
__device__ __forceinline__ uint32_t smem_u32(const void* p) {
    uint32_t a;
    asm("{ .reg .u64 t; cvta.to.shared.u64 t, %1; cvt.u32.u64 %0, t; }" : "=r"(a) : "l"(p));
    return a;
}

// ===================== tensor-core bf16x3 GEMM (BK=32) ======================
#define BK 32
#define LDSE 40
#define PARTB (64*LDSE*2)
#define STAGEB (4*PARTB)

__device__ __forceinline__ void load_chunk(
    const float* __restrict__ A, const float* __restrict__ A2, int lda,
    int row0a, int Ma,
    const float* __restrict__ W, int ldw, int row0w, int Nw,
    int k0, int tid, float4* ra, float4* rw)
{
    int r = tid >> 1, half = tid & 1;
    int ga = min(row0a + r, Ma - 1);
    int gw = min(row0w + r, Nw - 1);
    const float4* pa = (const float4*)(A + (size_t)ga * lda + k0 + half * 16);
    const float4* pw = (const float4*)(W + (size_t)gw * ldw + k0 + half * 16);
    #pragma unroll
    for (int u = 0; u < 4; u++) { ra[u] = pa[u]; rw[u] = pw[u]; }
    if (A2) {
        const float4* p2 = (const float4*)(A2 + (size_t)ga * lda + k0 + half * 16);
        #pragma unroll
        for (int u = 0; u < 4; u++) {
            float4 t = p2[u];
            ra[u].x += t.x; ra[u].y += t.y; ra[u].z += t.z; ra[u].w += t.w;
        }
    }
}

__device__ __forceinline__ void store_chunk(uint32_t s_hi, uint32_t s_lo,
                                            const float4* rv, int tid)
{
    int r = tid >> 1, half = tid & 1;
    uint32_t off = (uint32_t)r * (LDSE * 2) + half * 32;
    #pragma unroll
    for (int u = 0; u < 4; u++) {
        float4 v = rv[u];
        ushort4 hh, ll;
        split1(v.x, hh.x, ll.x); split1(v.y, hh.y, ll.y);
        split1(v.z, hh.z, ll.z); split1(v.w, hh.w, ll.w);
        asm volatile("st.shared.v4.u16 [%0], {%1,%2,%3,%4};"
                     :: "r"(s_hi + off + u * 8), "h"(hh.x), "h"(hh.y), "h"(hh.z), "h"(hh.w));
        asm volatile("st.shared.v4.u16 [%0], {%1,%2,%3,%4};"
                     :: "r"(s_lo + off + u * 8), "h"(ll.x), "h"(ll.y), "h"(ll.z), "h"(ll.w));
    }
}

__device__ __forceinline__ void gemm_mma_body(
    const float* __restrict__ A, const float* __restrict__ A2, int lda,
    const float* __restrict__ W, int ldw,
    const float* __restrict__ bias, float* __restrict__ C, size_t ldcr, int ldcc,
    int bm, int bn, int M, int N, int kbeg, int kend, int act)
{
    __shared__ __align__(16) char smem[2 * STAGEB];
    uint32_t sb = smem_u32(smem);
    int tid = threadIdx.x;                  // 128
    int lane = tid & 31, wid = tid >> 5;
    int wm = wid >> 1, wn = wid & 1;

    float acc[2][4][4] = {};

    uint32_t a_off = ((uint32_t)(wm * 32 + (lane & 15)) * LDSE + ((lane & 16) >> 1)) * 2;
    uint32_t b_off = ((uint32_t)(wn * 32 + (lane & 7) + ((lane & 16) >> 1)) * LDSE) * 2
                     + (lane & 8) * 2;

    int nch = (kend - kbeg) / BK;
    float4 ra[4], rw[4];
    load_chunk(A, A2, lda, bm, M, W, ldw, bn, N, kbeg, tid, ra, rw);
    store_chunk(sb, sb + PARTB, ra, tid);
    store_chunk(sb + 2 * PARTB, sb + 3 * PARTB, rw, tid);

    for (int c = 0; c < nch; c++) {
        uint32_t cb = sb + (uint32_t)(c & 1) * STAGEB;
        __syncthreads();
        bool more = (c + 1 < nch);
        if (more)
            load_chunk(A, A2, lda, bm, M, W, ldw, bn, N, kbeg + (c + 1) * BK, tid, ra, rw);
        #pragma unroll
        for (int ks = 0; ks < 2; ks++) {
            uint32_t a_hi[2][4], a_lo[2][4], b_hi[4][2], b_lo[4][2];
            #pragma unroll
            for (int tm = 0; tm < 2; tm++) {
                uint32_t ad = cb + a_off + (uint32_t)tm * 16 * LDSE * 2 + ks * 32;
                ldsm_x4(a_hi[tm][0], a_hi[tm][1], a_hi[tm][2], a_hi[tm][3], ad);
                ldsm_x4(a_lo[tm][0], a_lo[tm][1], a_lo[tm][2], a_lo[tm][3], ad + PARTB);
            }
            #pragma unroll
            for (int tp = 0; tp < 2; tp++) {
                uint32_t bd = cb + 2 * PARTB + b_off
                            + (uint32_t)tp * 16 * LDSE * 2 + ks * 32;
                ldsm_x4(b_hi[2*tp][0], b_hi[2*tp][1], b_hi[2*tp+1][0], b_hi[2*tp+1][1], bd);
                ldsm_x4(b_lo[2*tp][0], b_lo[2*tp][1], b_lo[2*tp+1][0], b_lo[2*tp+1][1],
                        bd + PARTB);
            }
            #pragma unroll
            for (int tm = 0; tm < 2; tm++)
                #pragma unroll
                for (int tn = 0; tn < 4; tn++) {
                    mma_bf16(acc[tm][tn], a_hi[tm], b_hi[tn]);
                    mma_bf16(acc[tm][tn], a_hi[tm], b_lo[tn]);
                    mma_bf16(acc[tm][tn], a_lo[tm], b_hi[tn]);
                }
        }
        if (more) {
            uint32_t nb = sb + (uint32_t)((c + 1) & 1) * STAGEB;
            store_chunk(nb, nb + PARTB, ra, tid);
            store_chunk(nb + 2 * PARTB, nb + 3 * PARTB, rw, tid);
        }
    }

    int mrow = bm + wm * 32 + (lane >> 2);
    int ncol = bn + wn * 32 + (lane & 3) * 2;
    #pragma unroll
    for (int tm = 0; tm < 2; tm++) {
        #pragma unroll
        for (int half = 0; half < 2; half++) {
            int m = mrow + tm * 16 + half * 8;
            if (m >= M) continue;
            size_t rb = (size_t)m * ldcr;
            #pragma unroll
            for (int tn = 0; tn < 4; tn++) {
                int n = ncol + tn * 8;
                float v0 = acc[tm][tn][half * 2 + 0];
                float v1 = acc[tm][tn][half * 2 + 1];
                if (bias) { v0 += bias[n]; v1 += bias[n + 1]; }
                if (act) { v0 = fmaxf(v0, 0.f); v1 = fmaxf(v1, 0.f); }
                if (ldcc == 1 && n + 1 < N) {
                    *(float2*)(C + rb + n) = make_float2(v0, v1);
                } else {
                    if (n < N)     C[rb + (size_t)n * ldcc]       = v0;
                    if (n + 1 < N) C[rb + (size_t)(n + 1) * ldcc] = v1;
                }
            }
        }
    }
}

// ===================== global kernels ========================================
__global__ void __launch_bounds__(128) gemm_tc(
    const float* A, const float* W, const float* bias, float* C,
    int M, int N, int K, int act)
{
    gemm_mma_body(A, nullptr, K, W, K, bias, C, N, 1,
                  blockIdx.y * 64, blockIdx.x * 64, M, N, 0, K, act);
}

__global__ void __launch_bounds__(128) gemm_tc_splitk(
    const float* A, const float* W, float* part, int M, int N, int K, int KS)
{
    int chunk = K / KS;
    int z = blockIdx.z;
    gemm_mma_body(A, nullptr, K, W, K, nullptr, part + (size_t)z * M * N, N, 1,
                  blockIdx.y * 64, blockIdx.x * 64, M, N, z * chunk, (z + 1) * chunk, 0);
}

// Wo projection with A = slab0 + slab1 (attn K-split partial sum), split-K
__global__ void __launch_bounds__(128) gemm_wo2(
    const float* A0, const float* A1s, const float* W, float* part,
    int M, int N, int K, int KS)
{
    int chunk = K / KS;
    int z = blockIdx.z;
    gemm_mma_body(A0, A1s, K, W, K, nullptr, part + (size_t)z * M * N, N, 1,
                  blockIdx.y * 64, blockIdx.x * 64, M, N, z * chunk, (z + 1) * chunk, 0);
}

// fused q/k/vs/vo projections + knowledge projection: 1D grid, 384 CTAs
__global__ void __launch_bounds__(128) gemm_layer_a(
    const float* __restrict__ h, const float* __restrict__ knowledge,
    const float* __restrict__ W0, const float* __restrict__ W1,
    const float* __restrict__ W2, const float* __restrict__ W3,
    const float* __restrict__ Wkn,
    float* __restrict__ qkv, float* __restrict__ kproj)
{
    int idx = blockIdx.x;
    if (idx < 256) {
        int z = idx >> 6, t = idx & 63;
        const float* W = (z == 0) ? W0 : (z == 1) ? W1 : (z == 2) ? W2 : W3;
        gemm_mma_body(h, nullptr, Esz, W, Esz, nullptr,
                      qkv + (size_t)z * Msz * Esz, Esz, 1,
                      (t >> 3) * 64, (t & 7) * 64, Msz, Esz, 0, Esz, 0);
    } else {
        int t = idx - 256;
        gemm_mma_body(knowledge, nullptr, Esz, Wkn, Esz, nullptr, kproj, Esz, 1,
                      (t >> 3) * 64, (t & 7) * 64, 1000, Esz, 0, Esz, 0);
    }
}

// combined qk + qkp (double-buffered BK=32 body): grid (18, 2, 32)
__global__ void __launch_bounds__(128) gemm_qkqkp(
    const float* __restrict__ q, const float* __restrict__ k,
    const float* __restrict__ kproj,
    float* __restrict__ qk, float* __restrict__ qkp)
{
    int z = blockIdx.z, b = z >> 3, h = z & 7;
    const float* qa = q + (size_t)b * Ssz * Esz + h * HDsz;
    int bm = blockIdx.y * 64;
    if (blockIdx.x < 16) {
        gemm_mma_body(qa, nullptr, Esz, kproj + h * HDsz, Esz, nullptr,
                      qkp + (size_t)b * Ssz * 8000 + h, 8000, 8,
                      bm, blockIdx.x * 64, Ssz, 1000, 0, HDsz, 0);
    } else {
        gemm_mma_body(qa, nullptr, Esz, k + (size_t)b * Ssz * Esz + h * HDsz, Esz,
                      nullptr, qk + (size_t)z * Ssz * Ssz, Ssz, 1,
                      bm, (blockIdx.x - 16) * 64, Ssz, Ssz, 0, HDsz, 0);
    }
}

// attention value GEMM, K-split over KEXT: grid (2, 2, 32) = 128 CTAs
__global__ void __launch_bounds__(128) gemm_attn(
    const float* __restrict__ Aext, const float* __restrict__ Wext,
    float* __restrict__ partout)
{
    int z2 = blockIdx.x;                 // K-split: [0,160) / [160,288)
    int z = blockIdx.z, b = z >> 3, h = z & 7;
    int kbeg = z2 ? 160 : 0;
    int kend = z2 ? 288 : 160;
    gemm_mma_body(Aext + (size_t)z * Ssz * KEXT, nullptr, KEXT,
                  Wext + (size_t)z * HDsz * KEXT, KEXT,
                  nullptr,
                  partout + (size_t)z2 * Msz * Esz + (size_t)b * Ssz * Esz + h * HDsz,
                  Esz, 1, blockIdx.y * 64, 0, Ssz, HDsz, kbeg, kend, 0);
}

// ======== combined scores (blocks 0..511) + W_ext pack (blocks 512..543) ====
__global__ void __launch_bounds__(256) scores_pack(
    const float* __restrict__ qk, const float* __restrict__ qkp,
    const float* __restrict__ q,
    const int* __restrict__ know_adj, const int* __restrict__ pos_mask,
    const int* __restrict__ adj,
    const int* __restrict__ smk, const int* __restrict__ omk,
    const float* __restrict__ pe_k,
    const float* __restrict__ vs, const float* __restrict__ vo,
    const float* __restrict__ pe_v,
    float* __restrict__ Aext, float* __restrict__ Wext)
{
    __shared__ float sh[128 * 65];
    int blk = blockIdx.x;
    int tid = threadIdx.x;

    if (blk >= 512) {
        int z = blk - 512, b = z >> 3, h = z & 7;
        float* vsh = sh;
        float* wbase = Wext + (size_t)z * HDsz * KEXT;
        for (int idx = tid; idx < 128 * 64; idx += 256) {
            int j = idx >> 6, d = idx & 63;
            vsh[j * 65 + d] = vs[(size_t)(b * Ssz + j) * Esz + h * HDsz + d];
        }
        __syncthreads();
        {
            int w = tid >> 5, l = tid & 31;
            #pragma unroll
            for (int r = 0; r < 8; r++) {
                int d = w * 8 + r;
                float* dst = wbase + (size_t)d * KEXT;
                #pragma unroll
                for (int t = 0; t < 4; t++) {
                    int j = l + 32 * t;
                    dst[j] = vsh[j * 65 + d];
                }
            }
        }
        __syncthreads();
        for (int idx = tid; idx < 128 * 64; idx += 256) {
            int j = idx >> 6, d = idx & 63;
            vsh[j * 65 + d] = vo[(size_t)(b * Ssz + j) * Esz + h * HDsz + d];
        }
        __syncthreads();
        {
            int w = tid >> 5, l = tid & 31;
            #pragma unroll
            for (int r = 0; r < 8; r++) {
                int d = w * 8 + r;
                float* dst = wbase + (size_t)d * KEXT + 128;
                #pragma unroll
                for (int t = 0; t < 4; t++) {
                    int j = l + 32 * t;
                    dst[j] = vsh[j * 65 + d];
                }
            }
        }
        for (int idx = tid; idx < 64 * 32; idx += 256) {
            int d = idx >> 5, c = idx & 31;
            float v = (c < 11) ? pe_v[c * HDsz + d] : 0.f;
            wbase[(size_t)d * KEXT + 256 + c] = v;
        }
        return;
    }

    int i = blk & 127, b = blk >> 7;
    float* q_sh   = sh;
    float* qk_sh  = sh + 512;
    float* qkp_sh = sh + 1536;
    float* qr     = sh + 2688;
    int*   ka_sh  = (int*)(sh + 2776);
    int*   p_sh   = (int*)(sh + 2904);

    q_sh[tid]       = q[(size_t)(b * Ssz + i) * Esz + tid];
    q_sh[tid + 256] = q[(size_t)(b * Ssz + i) * Esz + tid + 256];
    if (tid < 128) {
        int ka = know_adj[(size_t)(b * Ssz + i) * Ssz + tid];
        ka_sh[tid] = min(max(ka, 0), 999);
        int p = pos_mask[i * Ssz + tid];
        p_sh[tid] = min(max(p, 0), 10);
    }
    {
        int h = tid >> 5, j4 = (tid & 31) * 4;
        float4 v = *(const float4*)(qk + ((size_t)(b * Hn + h) * Ssz + i) * Ssz + j4);
        *(float4*)(qk_sh + h * 128 + j4) = v;
    }
    if (tid < 168) {
        int h = tid / 21, c = tid % 21;
        Aext[((size_t)(b * Hn + h) * Ssz + i) * KEXT + 267 + c] = 0.f;
    }
    __syncthreads();

    {
        int j = tid >> 1, half = tid & 1;
        float4 g = *(const float4*)(qkp + (size_t)(b * Ssz + i) * 8000
                                    + ka_sh[j] * 8 + half * 4);
        float* dst = qkp_sh + j * 9 + half * 4;
        dst[0] = g.x; dst[1] = g.y; dst[2] = g.z; dst[3] = g.w;
    }
    if (tid < 88) {
        int h = tid / 11, p = tid % 11;
        float s = 0.f;
        const float4* pk = (const float4*)(pe_k + p * HDsz);
        const float4* qv = (const float4*)(q_sh + h * 64);
        #pragma unroll
        for (int v = 0; v < 16; v++) {
            float4 e = pk[v], qq = qv[v];
            s += qq.x * e.x + qq.y * e.y + qq.z * e.z + qq.w * e.w;
        }
        qr[h * 11 + p] = s;
    }
    __syncthreads();

    {
        int w = tid >> 5, l = tid & 31;
        float s[4];
        float m = -3.4e38f;
        #pragma unroll
        for (int t = 0; t < 4; t++) {
            int j = l + 32 * t;
            float ss = (qk_sh[w * 128 + j] + qkp_sh[j * 9 + w]
                        + qr[w * 11 + p_sh[j]]) * 0.125f;
            if (adj[(size_t)(b * Ssz + i) * Ssz + j] == 0) ss -= 1e30f;
            s[t] = ss;
            m = fmaxf(m, ss);
        }
        #pragma unroll
        for (int o = 16; o; o >>= 1) m = fmaxf(m, __shfl_xor_sync(0xffffffffu, m, o));
        float sum = 0.f;
        float e[4];
        #pragma unroll
        for (int t = 0; t < 4; t++) { e[t] = __expf(s[t] - m); sum += e[t]; }
        #pragma unroll
        for (int o = 16; o; o >>= 1) sum += __shfl_xor_sync(0xffffffffu, sum, o);
        float inv = 1.f / sum;
        size_t abase = ((size_t)(b * Hn + w) * Ssz + i) * KEXT;
        #pragma unroll
        for (int t = 0; t < 4; t++) {
            int j = l + 32 * t;
            float attn = e[t] * inv;
            Aext[abase + j]       = attn * (float)smk[(size_t)(b * Ssz + i) * Ssz + j];
            Aext[abase + 128 + j] = attn * (float)omk[(size_t)(b * Ssz + i) * Ssz + j];
            qk_sh[w * 128 + j] = attn;
        }
    }
    __syncthreads();

    if (tid < 88) {
        int h = tid / 11, p = tid % 11;
        float s = 0.f;
        for (int j = 0; j < 128; j++)
            if (p_sh[j] == p) s += qk_sh[h * 128 + j];
        Aext[((size_t)(b * Hn + h) * Ssz + i) * KEXT + 256 + p] = s;
    }
}

// ===== fused split-K reduce + bias + residual + layernorm ===================
__global__ void ln_red_kernel(const float* __restrict__ x, const float* __restrict__ part,
                              int KS, const float* __restrict__ bias,
                              const float* __restrict__ g, const float* __restrict__ bt,
                              float* __restrict__ dst)
{
    const int MN = Msz * Esz;
    int row = blockIdx.x;
    int tid = threadIdx.x;   // 256
    __shared__ float red[8];
    size_t i0 = (size_t)row * Esz + tid;
    size_t i1 = i0 + 256;
    float v0 = x[i0], v1 = x[i1];
    for (int z = 0; z < KS; z++) {
        v0 += part[(size_t)z * MN + i0];
        v1 += part[(size_t)z * MN + i1];
    }
    if (bias) { v0 += bias[tid]; v1 += bias[tid + 256]; }
    float s = v0 + v1;
    #pragma unroll
    for (int o = 16; o; o >>= 1) s += __shfl_xor_sync(0xffffffffu, s, o);
    if ((tid & 31) == 0) red[tid >> 5] = s;
    __syncthreads();
    float mean = 0.f;
    #pragma unroll
    for (int w = 0; w < 8; w++) mean += red[w];
    mean *= (1.f / 512.f);
    __syncthreads();
    float e0 = v0 - mean, e1 = v1 - mean;
    float s2 = e0 * e0 + e1 * e1;
    #pragma unroll
    for (int o = 16; o; o >>= 1) s2 += __shfl_xor_sync(0xffffffffu, s2, o);
    if ((tid & 31) == 0) red[tid >> 5] = s2;
    __syncthreads();
    float var = 0.f;
    #pragma unroll
    for (int w = 0; w < 8; w++) var += red[w];
    var *= (1.f / 512.f);
    float rstd = rsqrtf(var + 1e-5f);
    dst[i0] = e0 * rstd * g[tid] + bt[tid];
    dst[i1] = e1 * rstd * g[tid + 256] + bt[tid + 256];
}

// ===================== host orchestration ===================================
extern "C" void kernel_launch(void* const* d_in, const int* in_sizes, int n_in,
                              void* d_out, int out_size)
{
    const float* x        = (const float*)d_in[0];
    const int*   adj      = (const int*)d_in[1];
    const int*   smk      = (const int*)d_in[2];
    const int*   omk      = (const int*)d_in[3];
    const float* knowledge= (const float*)d_in[4];
    const int*   know_adj = (const int*)d_in[5];
    const int*   pos_mask = (const int*)d_in[6];
    const float* pe_k     = (const float*)d_in[7];
    const float* pe_v     = (const float*)d_in[8];
    const float* Wq       = (const float*)d_in[9];
    const float* Wk       = (const float*)d_in[10];
    const float* Wvs      = (const float*)d_in[11];
    const float* Wvo      = (const float*)d_in[12];
    const float* Wo       = (const float*)d_in[13];
    const float* Wkn      = (const float*)d_in[14];
    const float* ln1g     = (const float*)d_in[15];
    const float* ln1b     = (const float*)d_in[16];
    const float* w1       = (const float*)d_in[17];
    const float* b1       = (const float*)d_in[18];
    const float* w2       = (const float*)d_in[19];
    const float* b2       = (const float*)d_in[20];
    const float* ln2g     = (const float*)d_in[21];
    const float* ln2b     = (const float*)d_in[22];
    float* out = (float*)d_out;

    float *h, *qkv, *kproj, *ff, *part, *qkbuf, *asump, *qkp, *Aext, *Wext;
    cudaGetSymbolAddress((void**)&h, g_h);
    cudaGetSymbolAddress((void**)&qkv, g_qkv);
    cudaGetSymbolAddress((void**)&kproj, g_kproj);
    cudaGetSymbolAddress((void**)&ff, g_ff);
    cudaGetSymbolAddress((void**)&part, g_part);
    cudaGetSymbolAddress((void**)&qkbuf, g_qk);
    cudaGetSymbolAddress((void**)&asump, g_asump);
    cudaGetSymbolAddress((void**)&qkp, g_qkp);
    cudaGetSymbolAddress((void**)&Aext, g_Aext);
    cudaGetSymbolAddress((void**)&Wext, g_Wext);

    const size_t EE = (size_t)Esz * Esz;
    const size_t FE = (size_t)FFsz * Esz;
    for (int l = 0; l < Lnum; l++) {
        const float* hin = (l == 0) ? x : h;
        const float* wq  = Wq  + (size_t)l * EE;
        const float* wk  = Wk  + (size_t)l * EE;
        const float* wvs = Wvs + (size_t)l * EE;
        const float* wvo = Wvo + (size_t)l * EE;
        const float* wo  = Wo  + (size_t)l * EE;
        const float* wkn = Wkn + (size_t)l * EE;

        // proj4 + kproj (384 CTAs, direct output)
        gemm_layer_a<<<384, 128>>>(hin, knowledge, wq, wk, wvs, wvo, wkn, qkv, kproj);
        // qk + qkp (1152 CTAs, double-buffered body)
        gemm_qkqkp<<<dim3(18, 2, 32), 128>>>(qkv, qkv + (size_t)Msz * Esz, kproj,
                                             qkbuf, qkp);
        scores_pack<<<544, 256>>>(
            qkbuf, qkp, qkv, know_adj, pos_mask, adj, smk, omk, pe_k,
            qkv + 2 * (size_t)Msz * Esz, qkv + 3 * (size_t)Msz * Esz, pe_v,
            Aext, Wext);
        // attention value GEMM, K-split=2 -> partials (128 CTAs)
        gemm_attn<<<dim3(2, 2, 32), 128>>>(Aext, Wext, asump);
        // Wo projection summing attn partials on the fly, split-K=2
        gemm_wo2<<<dim3(8, 8, 2), 128>>>(asump, asump + (size_t)Msz * Esz, wo, part,
                                         Msz, Esz, Esz, 2);
        ln_red_kernel<<<Msz, 256>>>(hin, part, 2, nullptr,
                                    ln1g + l * Esz, ln1b + l * Esz, h);
        // FFN1 (256 CTAs, fused bias+relu, direct output)
        gemm_tc<<<dim3(32, 8), 128>>>(h, w1 + (size_t)l * FE, b1 + (size_t)l * FFsz,
                                      ff, Msz, FFsz, Esz, 1);
        // FFN2 split-K=4 + fused reduce+bias+LN2
        gemm_tc_splitk<<<dim3(8, 8, 4), 128>>>(ff, w2 + (size_t)l * FE, part,
                                               Msz, Esz, FFsz, 4);
        float* dst = (l == Lnum - 1) ? out : h;
        ln_red_kernel<<<Msz, 256>>>(h, part, 4, b2 + l * Esz,
                                    ln2g + l * Esz, ln2b + l * Esz, dst);
    }
}

// round 17
// speedup vs baseline: 1.1033x; 1.0452x over previous
#include <cuda_runtime.h>
#include <cuda_bf16.h>
#include <cstdint>

#define Bsz 4
#define Ssz 128
#define Esz 512
#define Hn 8
#define HDsz 64
#define FFsz 2048
#define Lnum 4
#define Msz (Bsz*Ssz)   /* 512 rows */
#define KEXT 288        /* packed attn K: 128 + 128 + 11 -> pad 288 */

// ===================== scratch (static device memory) ======================
__device__ float g_h[Msz*Esz];
__device__ float g_qkv[4*Msz*Esz];
__device__ float g_kproj[1024*Esz];
__device__ float g_ff[Msz*FFsz];
__device__ float g_part[4*512*512];
__device__ float g_qk[Bsz*Hn*Ssz*Ssz];
__device__ float g_asump[2*Msz*Esz];
__device__ float g_qkp[512*8000];
__device__ float g_Aext[Bsz*Hn*Ssz*KEXT];
__device__ float g_Wext[Bsz*Hn*HDsz*KEXT];

// ===================== helpers ==============================================
__device__ __forceinline__ void split1(float x, unsigned short& h, unsigned short& l)
{
    __nv_bfloat16 hb = __float2bfloat16(x);
    h = __bfloat16_as_ushort(hb);
    l = __bfloat16_as_ushort(__float2bfloat16(x - __bfloat162float(hb)));
}
__device__ __forceinline__ void ldsm_x4(uint32_t& r0, uint32_t& r1,
                                        uint32_t& r2, uint32_t& r3, uint32_t addr)
{
    asm volatile("ldmatrix.sync.aligned.m8n8.x4.shared.b16 {%0,%1,%2,%3}, [%4];"
                 : "=r"(r0), "=r"(r1), "=r"(r2), "=r"(r3) : "r"(addr));
}
__device__ __forceinline__ void mma_bf16(float* c, const uint32_t* a, const uint32_t* b)
{
    asm volatile("mma.sync.aligned.m16n8k16.row.col.f32.bf16.bf16.f32 "
                 "{%0,%1,%2,%3},{%4,%5,%6,%7},{%8,%9},{%0,%1,%2,%3};"
                 : "+f"(c[0]), "+f"(c[1]), "+f"(c[2]), "+f"(c[3])
                 : "r"(a[0]), "r"(a[1]), "r"(a[2]), "r"(a[3]), "r"(b[0]), "r"(b[1]));
}
__device__ __forceinline__ uint32_t smem_u32(const void* p) {
    uint32_t a;
    asm("{ .reg .u64 t; cvta.to.shared.u64 t, %1; cvt.u32.u64 %0, t; }" : "=r"(a) : "l"(p));
    return a;
}

// =========== tensor-core bf16x3 GEMM (BK=32, 64x64 tile, 8 warps) ==========
#define BK 32
#define LDSE 40
#define PARTB (64*LDSE*2)
#define STAGEB (4*PARTB)

// 256 threads: each stages 8 floats of A and W (2 float4)
__device__ __forceinline__ void load_chunk(
    const float* __restrict__ A, const float* __restrict__ A2, int lda,
    int row0a, int Ma,
    const float* __restrict__ W, int ldw, int row0w, int Nw,
    int k0, int tid, float4* ra, float4* rw)
{
    int r = tid >> 2, q = tid & 3;
    int ga = min(row0a + r, Ma - 1);
    int gw = min(row0w + r, Nw - 1);
    const float4* pa = (const float4*)(A + (size_t)ga * lda + k0 + q * 8);
    const float4* pw = (const float4*)(W + (size_t)gw * ldw + k0 + q * 8);
    #pragma unroll
    for (int u = 0; u < 2; u++) { ra[u] = pa[u]; rw[u] = pw[u]; }
    if (A2) {
        const float4* p2 = (const float4*)(A2 + (size_t)ga * lda + k0 + q * 8);
        #pragma unroll
        for (int u = 0; u < 2; u++) {
            float4 t = p2[u];
            ra[u].x += t.x; ra[u].y += t.y; ra[u].z += t.z; ra[u].w += t.w;
        }
    }
}

__device__ __forceinline__ void store_chunk(uint32_t s_hi, uint32_t s_lo,
                                            const float4* rv, int tid)
{
    int r = tid >> 2, q = tid & 3;
    uint32_t off = (uint32_t)r * (LDSE * 2) + q * 16;
    #pragma unroll
    for (int u = 0; u < 2; u++) {
        float4 v = rv[u];
        ushort4 hh, ll;
        split1(v.x, hh.x, ll.x); split1(v.y, hh.y, ll.y);
        split1(v.z, hh.z, ll.z); split1(v.w, hh.w, ll.w);
        asm volatile("st.shared.v4.u16 [%0], {%1,%2,%3,%4};"
                     :: "r"(s_hi + off + u * 8), "h"(hh.x), "h"(hh.y), "h"(hh.z), "h"(hh.w));
        asm volatile("st.shared.v4.u16 [%0], {%1,%2,%3,%4};"
                     :: "r"(s_lo + off + u * 8), "h"(ll.x), "h"(ll.y), "h"(ll.z), "h"(ll.w));
    }
}

__device__ __forceinline__ void gemm_mma_body(
    const float* __restrict__ A, const float* __restrict__ A2, int lda,
    const float* __restrict__ W, int ldw,
    const float* __restrict__ bias, float* __restrict__ C, size_t ldcr, int ldcc,
    int bm, int bn, int M, int N, int kbeg, int kend, int act)
{
    __shared__ __align__(16) char smem[2 * STAGEB];
    uint32_t sb = smem_u32(smem);
    int tid = threadIdx.x;                  // 256
    int lane = tid & 31, wid = tid >> 5;    // 8 warps
    int wm = wid >> 2, wn = wid & 3;        // warp tile 32m x 16n

    float acc[2][2][4] = {};

    uint32_t a_off = ((uint32_t)(wm * 32 + (lane & 15)) * LDSE + ((lane & 16) >> 1)) * 2;
    uint32_t b_off = ((uint32_t)(wn * 16 + (lane & 7) + ((lane & 16) >> 1)) * LDSE) * 2
                     + (lane & 8) * 2;

    int nch = (kend - kbeg) / BK;
    float4 ra[2], rw[2];
    load_chunk(A, A2, lda, bm, M, W, ldw, bn, N, kbeg, tid, ra, rw);
    store_chunk(sb, sb + PARTB, ra, tid);
    store_chunk(sb + 2 * PARTB, sb + 3 * PARTB, rw, tid);

    for (int c = 0; c < nch; c++) {
        uint32_t cb = sb + (uint32_t)(c & 1) * STAGEB;
        __syncthreads();
        bool more = (c + 1 < nch);
        if (more)
            load_chunk(A, A2, lda, bm, M, W, ldw, bn, N, kbeg + (c + 1) * BK, tid, ra, rw);
        #pragma unroll
        for (int ks = 0; ks < 2; ks++) {
            uint32_t a_hi[2][4], a_lo[2][4], b_hi[2][2], b_lo[2][2];
            #pragma unroll
            for (int tm = 0; tm < 2; tm++) {
                uint32_t ad = cb + a_off + (uint32_t)tm * 16 * LDSE * 2 + ks * 32;
                ldsm_x4(a_hi[tm][0], a_hi[tm][1], a_hi[tm][2], a_hi[tm][3], ad);
                ldsm_x4(a_lo[tm][0], a_lo[tm][1], a_lo[tm][2], a_lo[tm][3], ad + PARTB);
            }
            {
                uint32_t bd = cb + 2 * PARTB + b_off + ks * 32;
                ldsm_x4(b_hi[0][0], b_hi[0][1], b_hi[1][0], b_hi[1][1], bd);
                ldsm_x4(b_lo[0][0], b_lo[0][1], b_lo[1][0], b_lo[1][1], bd + PARTB);
            }
            #pragma unroll
            for (int tm = 0; tm < 2; tm++)
                #pragma unroll
                for (int tn = 0; tn < 2; tn++) {
                    mma_bf16(acc[tm][tn], a_hi[tm], b_hi[tn]);
                    mma_bf16(acc[tm][tn], a_hi[tm], b_lo[tn]);
                    mma_bf16(acc[tm][tn], a_lo[tm], b_hi[tn]);
                }
        }
        if (more) {
            uint32_t nb = sb + (uint32_t)((c + 1) & 1) * STAGEB;
            store_chunk(nb, nb + PARTB, ra, tid);
            store_chunk(nb + 2 * PARTB, nb + 3 * PARTB, rw, tid);
        }
    }

    int mrow = bm + wm * 32 + (lane >> 2);
    int ncol = bn + wn * 16 + (lane & 3) * 2;
    #pragma unroll
    for (int tm = 0; tm < 2; tm++) {
        #pragma unroll
        for (int half = 0; half < 2; half++) {
            int m = mrow + tm * 16 + half * 8;
            if (m >= M) continue;
            size_t rb = (size_t)m * ldcr;
            #pragma unroll
            for (int tn = 0; tn < 2; tn++) {
                int n = ncol + tn * 8;
                float v0 = acc[tm][tn][half * 2 + 0];
                float v1 = acc[tm][tn][half * 2 + 1];
                if (bias) { v0 += bias[n]; v1 += bias[n + 1]; }
                if (act) { v0 = fmaxf(v0, 0.f); v1 = fmaxf(v1, 0.f); }
                if (ldcc == 1 && n + 1 < N) {
                    *(float2*)(C + rb + n) = make_float2(v0, v1);
                } else {
                    if (n < N)     C[rb + (size_t)n * ldcc]       = v0;
                    if (n + 1 < N) C[rb + (size_t)(n + 1) * ldcc] = v1;
                }
            }
        }
    }
}

// ===================== global kernels ========================================
__global__ void __launch_bounds__(256) gemm_tc(
    const float* A, const float* W, const float* bias, float* C,
    int M, int N, int K, int act)
{
    gemm_mma_body(A, nullptr, K, W, K, bias, C, N, 1,
                  blockIdx.y * 64, blockIdx.x * 64, M, N, 0, K, act);
}

__global__ void __launch_bounds__(256) gemm_tc_splitk(
    const float* A, const float* W, float* part, int M, int N, int K, int KS)
{
    int chunk = K / KS;
    int z = blockIdx.z;
    gemm_mma_body(A, nullptr, K, W, K, nullptr, part + (size_t)z * M * N, N, 1,
                  blockIdx.y * 64, blockIdx.x * 64, M, N, z * chunk, (z + 1) * chunk, 0);
}

__global__ void __launch_bounds__(256) gemm_wo2(
    const float* A0, const float* A1s, const float* W, float* part,
    int M, int N, int K, int KS)
{
    int chunk = K / KS;
    int z = blockIdx.z;
    gemm_mma_body(A0, A1s, K, W, K, nullptr, part + (size_t)z * M * N, N, 1,
                  blockIdx.y * 64, blockIdx.x * 64, M, N, z * chunk, (z + 1) * chunk, 0);
}

__global__ void __launch_bounds__(256) gemm_layer_a(
    const float* __restrict__ h, const float* __restrict__ knowledge,
    const float* __restrict__ W0, const float* __restrict__ W1,
    const float* __restrict__ W2, const float* __restrict__ W3,
    const float* __restrict__ Wkn,
    float* __restrict__ qkv, float* __restrict__ kproj)
{
    int idx = blockIdx.x;
    if (idx < 256) {
        int z = idx >> 6, t = idx & 63;
        const float* W = (z == 0) ? W0 : (z == 1) ? W1 : (z == 2) ? W2 : W3;
        gemm_mma_body(h, nullptr, Esz, W, Esz, nullptr,
                      qkv + (size_t)z * Msz * Esz, Esz, 1,
                      (t >> 3) * 64, (t & 7) * 64, Msz, Esz, 0, Esz, 0);
    } else {
        int t = idx - 256;
        gemm_mma_body(knowledge, nullptr, Esz, Wkn, Esz, nullptr, kproj, Esz, 1,
                      (t >> 3) * 64, (t & 7) * 64, 1000, Esz, 0, Esz, 0);
    }
}

__global__ void __launch_bounds__(256) gemm_qkqkp(
    const float* __restrict__ q, const float* __restrict__ k,
    const float* __restrict__ kproj,
    float* __restrict__ qk, float* __restrict__ qkp)
{
    int z = blockIdx.z, b = z >> 3, h = z & 7;
    const float* qa = q + (size_t)b * Ssz * Esz + h * HDsz;
    int bm = blockIdx.y * 64;
    if (blockIdx.x < 16) {
        gemm_mma_body(qa, nullptr, Esz, kproj + h * HDsz, Esz, nullptr,
                      qkp + (size_t)b * Ssz * 8000 + h, 8000, 8,
                      bm, blockIdx.x * 64, Ssz, 1000, 0, HDsz, 0);
    } else {
        gemm_mma_body(qa, nullptr, Esz, k + (size_t)b * Ssz * Esz + h * HDsz, Esz,
                      nullptr, qk + (size_t)z * Ssz * Ssz, Ssz, 1,
                      bm, (blockIdx.x - 16) * 64, Ssz, Ssz, 0, HDsz, 0);
    }
}

__global__ void __launch_bounds__(256) gemm_attn(
    const float* __restrict__ Aext, const float* __restrict__ Wext,
    float* __restrict__ partout)
{
    int z2 = blockIdx.x;                 // K-split: [0,160) / [160,288)
    int z = blockIdx.z, b = z >> 3, h = z & 7;
    int kbeg = z2 ? 160 : 0;
    int kend = z2 ? 288 : 160;
    gemm_mma_body(Aext + (size_t)z * Ssz * KEXT, nullptr, KEXT,
                  Wext + (size_t)z * HDsz * KEXT, KEXT,
                  nullptr,
                  partout + (size_t)z2 * Msz * Esz + (size_t)b * Ssz * Esz + h * HDsz,
                  Esz, 1, blockIdx.y * 64, 0, Ssz, HDsz, kbeg, kend, 0);
}

// ======== combined scores (blocks 0..511) + W_ext pack (blocks 512..543) ====
__global__ void __launch_bounds__(256) scores_pack(
    const float* __restrict__ qk, const float* __restrict__ qkp,
    const float* __restrict__ q,
    const int* __restrict__ know_adj, const int* __restrict__ pos_mask,
    const int* __restrict__ adj,
    const int* __restrict__ smk, const int* __restrict__ omk,
    const float* __restrict__ pe_k,
    const float* __restrict__ vs, const float* __restrict__ vo,
    const float* __restrict__ pe_v,
    float* __restrict__ Aext, float* __restrict__ Wext)
{
    __shared__ float sh[128 * 65];
    int blk = blockIdx.x;
    int tid = threadIdx.x;

    if (blk >= 512) {
        int z = blk - 512, b = z >> 3, h = z & 7;
        float* vsh = sh;
        float* wbase = Wext + (size_t)z * HDsz * KEXT;
        for (int idx = tid; idx < 128 * 64; idx += 256) {
            int j = idx >> 6, d = idx & 63;
            vsh[j * 65 + d] = vs[(size_t)(b * Ssz + j) * Esz + h * HDsz + d];
        }
        __syncthreads();
        {
            int w = tid >> 5, l = tid & 31;
            #pragma unroll
            for (int r = 0; r < 8; r++) {
                int d = w * 8 + r;
                float* dst = wbase + (size_t)d * KEXT;
                #pragma unroll
                for (int t = 0; t < 4; t++) {
                    int j = l + 32 * t;
                    dst[j] = vsh[j * 65 + d];
                }
            }
        }
        __syncthreads();
        for (int idx = tid; idx < 128 * 64; idx += 256) {
            int j = idx >> 6, d = idx & 63;
            vsh[j * 65 + d] = vo[(size_t)(b * Ssz + j) * Esz + h * HDsz + d];
        }
        __syncthreads();
        {
            int w = tid >> 5, l = tid & 31;
            #pragma unroll
            for (int r = 0; r < 8; r++) {
                int d = w * 8 + r;
                float* dst = wbase + (size_t)d * KEXT + 128;
                #pragma unroll
                for (int t = 0; t < 4; t++) {
                    int j = l + 32 * t;
                    dst[j] = vsh[j * 65 + d];
                }
            }
        }
        for (int idx = tid; idx < 64 * 32; idx += 256) {
            int d = idx >> 5, c = idx & 31;
            float v = (c < 11) ? pe_v[c * HDsz + d] : 0.f;
            wbase[(size_t)d * KEXT + 256 + c] = v;
        }
        return;
    }

    int i = blk & 127, b = blk >> 7;
    float* q_sh   = sh;
    float* qk_sh  = sh + 512;
    float* qkp_sh = sh + 1536;
    float* qr     = sh + 2688;
    int*   ka_sh  = (int*)(sh + 2776);
    int*   p_sh   = (int*)(sh + 2904);

    q_sh[tid]       = q[(size_t)(b * Ssz + i) * Esz + tid];
    q_sh[tid + 256] = q[(size_t)(b * Ssz + i) * Esz + tid + 256];
    if (tid < 128) {
        int ka = know_adj[(size_t)(b * Ssz + i) * Ssz + tid];
        ka_sh[tid] = min(max(ka, 0), 999);
        int p = pos_mask[i * Ssz + tid];
        p_sh[tid] = min(max(p, 0), 10);
    }
    {
        int h = tid >> 5, j4 = (tid & 31) * 4;
        float4 v = *(const float4*)(qk + ((size_t)(b * Hn + h) * Ssz + i) * Ssz + j4);
        *(float4*)(qk_sh + h * 128 + j4) = v;
    }
    if (tid < 168) {
        int h = tid / 21, c = tid % 21;
        Aext[((size_t)(b * Hn + h) * Ssz + i) * KEXT + 267 + c] = 0.f;
    }
    __syncthreads();

    {
        int j = tid >> 1, half = tid & 1;
        float4 g = *(const float4*)(qkp + (size_t)(b * Ssz + i) * 8000
                                    + ka_sh[j] * 8 + half * 4);
        float* dst = qkp_sh + j * 9 + half * 4;
        dst[0] = g.x; dst[1] = g.y; dst[2] = g.z; dst[3] = g.w;
    }
    if (tid < 88) {
        int h = tid / 11, p = tid % 11;
        float s = 0.f;
        const float4* pk = (const float4*)(pe_k + p * HDsz);
        const float4* qv = (const float4*)(q_sh + h * 64);
        #pragma unroll
        for (int v = 0; v < 16; v++) {
            float4 e = pk[v], qq = qv[v];
            s += qq.x * e.x + qq.y * e.y + qq.z * e.z + qq.w * e.w;
        }
        qr[h * 11 + p] = s;
    }
    __syncthreads();

    {
        int w = tid >> 5, l = tid & 31;
        float s[4];
        float m = -3.4e38f;
        #pragma unroll
        for (int t = 0; t < 4; t++) {
            int j = l + 32 * t;
            float ss = (qk_sh[w * 128 + j] + qkp_sh[j * 9 + w]
                        + qr[w * 11 + p_sh[j]]) * 0.125f;
            if (adj[(size_t)(b * Ssz + i) * Ssz + j] == 0) ss -= 1e30f;
            s[t] = ss;
            m = fmaxf(m, ss);
        }
        #pragma unroll
        for (int o = 16; o; o >>= 1) m = fmaxf(m, __shfl_xor_sync(0xffffffffu, m, o));
        float sum = 0.f;
        float e[4];
        #pragma unroll
        for (int t = 0; t < 4; t++) { e[t] = __expf(s[t] - m); sum += e[t]; }
        #pragma unroll
        for (int o = 16; o; o >>= 1) sum += __shfl_xor_sync(0xffffffffu, sum, o);
        float inv = 1.f / sum;
        size_t abase = ((size_t)(b * Hn + w) * Ssz + i) * KEXT;
        #pragma unroll
        for (int t = 0; t < 4; t++) {
            int j = l + 32 * t;
            float attn = e[t] * inv;
            Aext[abase + j]       = attn * (float)smk[(size_t)(b * Ssz + i) * Ssz + j];
            Aext[abase + 128 + j] = attn * (float)omk[(size_t)(b * Ssz + i) * Ssz + j];
            qk_sh[w * 128 + j] = attn;
        }
    }
    __syncthreads();

    if (tid < 88) {
        int h = tid / 11, p = tid % 11;
        float s = 0.f;
        for (int j = 0; j < 128; j++)
            if (p_sh[j] == p) s += qk_sh[h * 128 + j];
        Aext[((size_t)(b * Hn + h) * Ssz + i) * KEXT + 256 + p] = s;
    }
}

// ===== fused split-K reduce + bias + residual + layernorm ===================
__global__ void ln_red_kernel(const float* __restrict__ x, const float* __restrict__ part,
                              int KS, const float* __restrict__ bias,
                              const float* __restrict__ g, const float* __restrict__ bt,
                              float* __restrict__ dst)
{
    const int MN = Msz * Esz;
    int row = blockIdx.x;
    int tid = threadIdx.x;   // 256
    __shared__ float red[8];
    size_t i0 = (size_t)row * Esz + tid;
    size_t i1 = i0 + 256;
    float v0 = x[i0], v1 = x[i1];
    for (int z = 0; z < KS; z++) {
        v0 += part[(size_t)z * MN + i0];
        v1 += part[(size_t)z * MN + i1];
    }
    if (bias) { v0 += bias[tid]; v1 += bias[tid + 256]; }
    float s = v0 + v1;
    #pragma unroll
    for (int o = 16; o; o >>= 1) s += __shfl_xor_sync(0xffffffffu, s, o);
    if ((tid & 31) == 0) red[tid >> 5] = s;
    __syncthreads();
    float mean = 0.f;
    #pragma unroll
    for (int w = 0; w < 8; w++) mean += red[w];
    mean *= (1.f / 512.f);
    __syncthreads();
    float e0 = v0 - mean, e1 = v1 - mean;
    float s2 = e0 * e0 + e1 * e1;
    #pragma unroll
    for (int o = 16; o; o >>= 1) s2 += __shfl_xor_sync(0xffffffffu, s2, o);
    if ((tid & 31) == 0) red[tid >> 5] = s2;
    __syncthreads();
    float var = 0.f;
    #pragma unroll
    for (int w = 0; w < 8; w++) var += red[w];
    var *= (1.f / 512.f);
    float rstd = rsqrtf(var + 1e-5f);
    dst[i0] = e0 * rstd * g[tid] + bt[tid];
    dst[i1] = e1 * rstd * g[tid + 256] + bt[tid + 256];
}

// ===================== host orchestration ===================================
extern "C" void kernel_launch(void* const* d_in, const int* in_sizes, int n_in,
                              void* d_out, int out_size)
{
    const float* x        = (const float*)d_in[0];
    const int*   adj      = (const int*)d_in[1];
    const int*   smk      = (const int*)d_in[2];
    const int*   omk      = (const int*)d_in[3];
    const float* knowledge= (const float*)d_in[4];
    const int*   know_adj = (const int*)d_in[5];
    const int*   pos_mask = (const int*)d_in[6];
    const float* pe_k     = (const float*)d_in[7];
    const float* pe_v     = (const float*)d_in[8];
    const float* Wq       = (const float*)d_in[9];
    const float* Wk       = (const float*)d_in[10];
    const float* Wvs      = (const float*)d_in[11];
    const float* Wvo      = (const float*)d_in[12];
    const float* Wo       = (const float*)d_in[13];
    const float* Wkn      = (const float*)d_in[14];
    const float* ln1g     = (const float*)d_in[15];
    const float* ln1b     = (const float*)d_in[16];
    const float* w1       = (const float*)d_in[17];
    const float* b1       = (const float*)d_in[18];
    const float* w2       = (const float*)d_in[19];
    const float* b2       = (const float*)d_in[20];
    const float* ln2g     = (const float*)d_in[21];
    const float* ln2b     = (const float*)d_in[22];
    float* out = (float*)d_out;

    float *h, *qkv, *kproj, *ff, *part, *qkbuf, *asump, *qkp, *Aext, *Wext;
    cudaGetSymbolAddress((void**)&h, g_h);
    cudaGetSymbolAddress((void**)&qkv, g_qkv);
    cudaGetSymbolAddress((void**)&kproj, g_kproj);
    cudaGetSymbolAddress((void**)&ff, g_ff);
    cudaGetSymbolAddress((void**)&part, g_part);
    cudaGetSymbolAddress((void**)&qkbuf, g_qk);
    cudaGetSymbolAddress((void**)&asump, g_asump);
    cudaGetSymbolAddress((void**)&qkp, g_qkp);
    cudaGetSymbolAddress((void**)&Aext, g_Aext);
    cudaGetSymbolAddress((void**)&Wext, g_Wext);

    const size_t EE = (size_t)Esz * Esz;
    const size_t FE = (size_t)FFsz * Esz;
    for (int l = 0; l < Lnum; l++) {
        const float* hin = (l == 0) ? x : h;
        const float* wq  = Wq  + (size_t)l * EE;
        const float* wk  = Wk  + (size_t)l * EE;
        const float* wvs = Wvs + (size_t)l * EE;
        const float* wvo = Wvo + (size_t)l * EE;
        const float* wo  = Wo  + (size_t)l * EE;
        const float* wkn = Wkn + (size_t)l * EE;

        gemm_layer_a<<<384, 256>>>(hin, knowledge, wq, wk, wvs, wvo, wkn, qkv, kproj);
        gemm_qkqkp<<<dim3(18, 2, 32), 256>>>(qkv, qkv + (size_t)Msz * Esz, kproj,
                                             qkbuf, qkp);
        scores_pack<<<544, 256>>>(
            qkbuf, qkp, qkv, know_adj, pos_mask, adj, smk, omk, pe_k,
            qkv + 2 * (size_t)Msz * Esz, qkv + 3 * (size_t)Msz * Esz, pe_v,
            Aext, Wext);
        gemm_attn<<<dim3(2, 2, 32), 256>>>(Aext, Wext, asump);
        gemm_wo2<<<dim3(8, 8, 2), 256>>>(asump, asump + (size_t)Msz * Esz, wo, part,
                                         Msz, Esz, Esz, 2);
        ln_red_kernel<<<Msz, 256>>>(hin, part, 2, nullptr,
                                    ln1g + l * Esz, ln1b + l * Esz, h);
        gemm_tc<<<dim3(32, 8), 256>>>(h, w1 + (size_t)l * FE, b1 + (size_t)l * FFsz,
                                      ff, Msz, FFsz, Esz, 1);
        gemm_tc_splitk<<<dim3(8, 8, 4), 256>>>(ff, w2 + (size_t)l * FE, part,
                                               Msz, Esz, FFsz, 4);
        float* dst = (l == Lnum - 1) ? out : h;
        ln_red_kernel<<<Msz, 256>>>(h, part, 4, b2 + l * Esz,
                                    ln2g + l * Esz, ln2b + l * Esz, dst);
    }
}